// round 8
// baseline (speedup 1.0000x reference)
#include <cuda_runtime.h>
#include <math.h>

#define POOLED   7
#define CHANNELS 256
#define BATCH    4
#define H        50
#define W        50
#define HW       (H*W)
#define SCALE    0.0625f

// NHWC scratch: featT[b][h][w][c]
__device__ float g_featT[(size_t)BATCH * HW * CHANNELS];

// ---------------- Transpose NCHW -> NHWC (tiled, conflict-free) -------------
__global__ void __launch_bounds__(256)
transpose_kernel(const float* __restrict__ feat)
{
    __shared__ float tile[32][33];

    int b   = blockIdx.z;
    int hw0 = blockIdx.x * 32;
    int c0  = blockIdx.y * 32;
    int tx  = threadIdx.x;   // 0..31
    int ty  = threadIdx.y;   // 0..7

    const float* in = feat + (size_t)b * CHANNELS * HW;

    #pragma unroll
    for (int i = 0; i < 32; i += 8) {
        int c  = c0 + ty + i;
        int hw = hw0 + tx;
        if (hw < HW)
            tile[ty + i][tx] = in[(size_t)c * HW + hw];
    }
    __syncthreads();

    float* outp = g_featT + (size_t)b * HW * CHANNELS;
    #pragma unroll
    for (int i = 0; i < 32; i += 8) {
        int hw = hw0 + ty + i;
        int c  = c0 + tx;
        if (hw < HW)
            outp[(size_t)hw * CHANNELS + c] = tile[tx][ty + i];
    }
}

// ---- RoI max-pool: block = (roi-pair, bin), 256 thr, half-block = 1 roi ----
__global__ void __launch_bounds__(256)
roipool_kernel5(const float* __restrict__ rois,
                float* __restrict__ out)
{
    __shared__ int soff[2][96];    // per-half padded pixel offsets (float2 units)

    int blk  = blockIdx.x;         // q*49 + bin, q = roi pair
    int q    = blk / 49;
    int bin  = blk - q * 49;
    int ph   = bin / POOLED;
    int pw   = bin - ph * POOLED;

    int t    = threadIdx.x;        // 0..255
    int half = t >> 7;             // 0 or 1
    int tt   = t & 127;            // 0..127 -> channels 2tt, 2tt+1
    int r    = 2 * q + half;

    const float* roi = rois + r * 5;
    int   b  = (int)roi[0];
    float x1 = floorf(__fadd_rn(__fmul_rn(roi[1], SCALE), 0.5f));
    float y1 = floorf(__fadd_rn(__fmul_rn(roi[2], SCALE), 0.5f));
    float x2 = floorf(__fadd_rn(__fmul_rn(roi[3], SCALE), 0.5f));
    float y2 = floorf(__fadd_rn(__fmul_rn(roi[4], SCALE), 0.5f));

    float roi_w = fmaxf(__fadd_rn(__fadd_rn(x2, -x1), 1.0f), 1.0f);
    float roi_h = fmaxf(__fadd_rn(__fadd_rn(y2, -y1), 1.0f), 1.0f);

    // Match XLA-CPU fast-math: x/7 lowered to x * fl32(1/7)
    const float inv7 = 1.0f / 7.0f;
    float bin_w = __fmul_rn(roi_w, inv7);
    float bin_h = __fmul_rn(roi_h, inv7);

    float pwf = (float)pw;
    float phf = (float)ph;

    float ws = fminf(fmaxf(__fadd_rn(floorf(__fmul_rn(pwf, bin_w)), x1), 0.0f), (float)W);
    float we = fminf(fmaxf(__fadd_rn(ceilf(__fmul_rn(__fadd_rn(pwf, 1.0f), bin_w)), x1), 0.0f), (float)W);
    float hs = fminf(fmaxf(__fadd_rn(floorf(__fmul_rn(phf, bin_h)), y1), 0.0f), (float)H);
    float he = fminf(fmaxf(__fadd_rn(ceilf(__fmul_rn(__fadd_rn(phf, 1.0f), bin_h)), y1), 0.0f), (float)H);

    int iws = (int)ws, iwe = (int)we;
    int ihs = (int)hs, ihe = (int)he;

    bool empty = (ihe <= ihs) || (iwe <= iws);   // uniform per half-block

    int bw    = iwe - iws;
    int n     = empty ? 0 : (ihe - ihs) * bw;    // <= 81
    int n_pad = (n + 3) & ~3;                    // <= 84 < 96

    // Build this half's offset table (one int div per thread, once).
    if (tt < n_pad) {
        int p = min(tt, n - 1);                  // pad by replicating last pixel
        int h = p / bw;
        int w = p - h * bw;
        soff[half][tt] = ((ihs + h) * W + (iws + w)) * 128;  // float2 units
    }
    __syncthreads();

    // out index: ((r*256 + c)*49 + bin), c = 2tt and 2tt+1
    float* o = out + (size_t)r * 12544 + (size_t)(2 * tt) * 49 + bin;

    if (empty) {
        o[0]  = 0.0f;
        o[49] = 0.0f;
        return;
    }

    const float2* base = (const float2*)(g_featT + (size_t)b * HW * CHANNELS) + tt;

    float2 m = make_float2(-INFINITY, -INFINITY);
    for (int p = 0; p < n_pad; p += 4) {
        int4 o4 = *(const int4*)&soff[half][p];   // LDS.128, warp-broadcast
        float2 a  = __ldg(base + o4.x);
        float2 bb = __ldg(base + o4.y);
        float2 cc = __ldg(base + o4.z);
        float2 dd = __ldg(base + o4.w);
        m.x = fmaxf(m.x, fmaxf(fmaxf(a.x, bb.x), fmaxf(cc.x, dd.x)));
        m.y = fmaxf(m.y, fmaxf(fmaxf(a.y, bb.y), fmaxf(cc.y, dd.y)));
    }

    o[0]  = m.x;
    o[49] = m.y;
}

extern "C" void kernel_launch(void* const* d_in, const int* in_sizes, int n_in,
                              void* d_out, int out_size)
{
    const float* feat = (const float*)d_in[0];
    const float* rois = (const float*)d_in[1];
    float* out = (float*)d_out;

    dim3 tgrid((HW + 31) / 32, CHANNELS / 32, BATCH);   // 79 x 8 x 4
    dim3 tblk(32, 8);
    transpose_kernel<<<tgrid, tblk>>>(feat);

    int blocks = 64 * 49;   // (roi-pair, bin) = 3136
    roipool_kernel5<<<blocks, 256>>>(rois, out);
}

// round 9
// speedup vs baseline: 1.2183x; 1.2183x over previous
#include <cuda_runtime.h>
#include <math.h>

#define POOLED   7
#define CHANNELS 256
#define BATCH    4
#define H        50
#define W        50
#define HW       (H*W)
#define SCALE    0.0625f

// NHWC scratch: featT[b][h][w][c]
__device__ float g_featT[(size_t)BATCH * HW * CHANNELS];
// Pool output scratch: g_outT[r][bin][c]  (128 * 49 * 256 f32 = 6.4 MB)
__device__ float g_outT[(size_t)128 * 49 * CHANNELS];

// ---------------- Transpose NCHW -> NHWC (tiled, conflict-free) -------------
__global__ void __launch_bounds__(256)
transpose_kernel(const float* __restrict__ feat)
{
    __shared__ float tile[32][33];

    int b   = blockIdx.z;
    int hw0 = blockIdx.x * 32;
    int c0  = blockIdx.y * 32;
    int tx  = threadIdx.x;   // 0..31
    int ty  = threadIdx.y;   // 0..7

    const float* in = feat + (size_t)b * CHANNELS * HW;

    #pragma unroll
    for (int i = 0; i < 32; i += 8) {
        int c  = c0 + ty + i;
        int hw = hw0 + tx;
        if (hw < HW)
            tile[ty + i][tx] = in[(size_t)c * HW + hw];
    }
    __syncthreads();

    float* outp = g_featT + (size_t)b * HW * CHANNELS;
    #pragma unroll
    for (int i = 0; i < 32; i += 8) {
        int hw = hw0 + ty + i;
        int c  = c0 + tx;
        if (hw < HW)
            outp[(size_t)hw * CHANNELS + c] = tile[tx][ty + i];
    }
}

// ------------- RoI max-pool: block = (roi, bin), coalesced stores -----------
__global__ void __launch_bounds__(128)
roipool_kernel6(const float* __restrict__ rois)
{
    __shared__ int soff[96];       // padded pixel offsets (float2 units), max 88

    int blk = blockIdx.x;          // r*49 + bin
    int r   = blk / 49;
    int bin = blk - r * 49;
    int ph  = bin / POOLED;
    int pw  = bin - ph * POOLED;
    int t   = threadIdx.x;         // 0..127 -> channels 2t, 2t+1

    const float* roi = rois + r * 5;
    int   b  = (int)roi[0];
    float x1 = floorf(__fadd_rn(__fmul_rn(roi[1], SCALE), 0.5f));
    float y1 = floorf(__fadd_rn(__fmul_rn(roi[2], SCALE), 0.5f));
    float x2 = floorf(__fadd_rn(__fmul_rn(roi[3], SCALE), 0.5f));
    float y2 = floorf(__fadd_rn(__fmul_rn(roi[4], SCALE), 0.5f));

    float roi_w = fmaxf(__fadd_rn(__fadd_rn(x2, -x1), 1.0f), 1.0f);
    float roi_h = fmaxf(__fadd_rn(__fadd_rn(y2, -y1), 1.0f), 1.0f);

    // Match XLA-CPU fast-math: x/7 lowered to x * fl32(1/7)
    const float inv7 = 1.0f / 7.0f;
    float bin_w = __fmul_rn(roi_w, inv7);
    float bin_h = __fmul_rn(roi_h, inv7);

    float pwf = (float)pw;
    float phf = (float)ph;

    float ws = fminf(fmaxf(__fadd_rn(floorf(__fmul_rn(pwf, bin_w)), x1), 0.0f), (float)W);
    float we = fminf(fmaxf(__fadd_rn(ceilf(__fmul_rn(__fadd_rn(pwf, 1.0f), bin_w)), x1), 0.0f), (float)W);
    float hs = fminf(fmaxf(__fadd_rn(floorf(__fmul_rn(phf, bin_h)), y1), 0.0f), (float)H);
    float he = fminf(fmaxf(__fadd_rn(ceilf(__fmul_rn(__fadd_rn(phf, 1.0f), bin_h)), y1), 0.0f), (float)H);

    int iws = (int)ws, iwe = (int)we;
    int ihs = (int)hs, ihe = (int)he;

    // Coalesced store target: g_outT[blk][c], c = 2t, 2t+1 -> one STG.64
    float2* o2 = (float2*)(g_outT + (size_t)blk * CHANNELS) + t;

    if (ihe <= ihs || iwe <= iws) {     // block-uniform
        *o2 = make_float2(0.0f, 0.0f);
        return;
    }

    int bw    = iwe - iws;                      // <= 9 after clamping
    int n     = (ihe - ihs) * bw;               // <= 81
    int n_pad = (n + 7) & ~7;                   // <= 88 < 96 (MLP-8 groups)

    // Build offset table: one int div per participating thread, once.
    if (t < n_pad) {
        int p = min(t, n - 1);                  // pad by replicating last pixel
        int h = p / bw;
        int w = p - h * bw;
        soff[t] = ((ihs + h) * W + (iws + w)) * 128;   // float2 units
    }
    __syncthreads();

    const float2* base = (const float2*)(g_featT + (size_t)b * HW * CHANNELS) + t;

    float2 m = make_float2(-INFINITY, -INFINITY);
    for (int p = 0; p < n_pad; p += 8) {
        int4 oa = *(const int4*)&soff[p];       // LDS.128, warp-broadcast
        int4 ob = *(const int4*)&soff[p + 4];
        // 8 independent LDG.64 in flight before any consume
        float2 v0 = __ldg(base + oa.x);
        float2 v1 = __ldg(base + oa.y);
        float2 v2 = __ldg(base + oa.z);
        float2 v3 = __ldg(base + oa.w);
        float2 v4 = __ldg(base + ob.x);
        float2 v5 = __ldg(base + ob.y);
        float2 v6 = __ldg(base + ob.z);
        float2 v7 = __ldg(base + ob.w);
        float ax = fmaxf(fmaxf(v0.x, v1.x), fmaxf(v2.x, v3.x));
        float bx = fmaxf(fmaxf(v4.x, v5.x), fmaxf(v6.x, v7.x));
        float ay = fmaxf(fmaxf(v0.y, v1.y), fmaxf(v2.y, v3.y));
        float by = fmaxf(fmaxf(v4.y, v5.y), fmaxf(v6.y, v7.y));
        m.x = fmaxf(m.x, fmaxf(ax, bx));
        m.y = fmaxf(m.y, fmaxf(ay, by));
    }

    *o2 = m;
}

// ------------- Output transpose: g_outT[r][bin][c] -> out[r][c][bin] --------
__global__ void __launch_bounds__(256)
out_transpose_kernel(float* __restrict__ out)
{
    __shared__ float tile[32][33];

    int r    = blockIdx.z;
    int bin0 = blockIdx.x * 32;     // 0 or 32
    int c0   = blockIdx.y * 32;
    int tx   = threadIdx.x;         // 0..31
    int ty   = threadIdx.y;         // 0..7

    const float* in = g_outT + (size_t)r * 49 * CHANNELS;

    #pragma unroll
    for (int i = 0; i < 32; i += 8) {
        int bin = bin0 + ty + i;
        int c   = c0 + tx;
        if (bin < 49)
            tile[ty + i][tx] = in[(size_t)bin * CHANNELS + c];
    }
    __syncthreads();

    float* op = out + (size_t)r * 12544;
    #pragma unroll
    for (int i = 0; i < 32; i += 8) {
        int c   = c0 + ty + i;
        int bin = bin0 + tx;
        if (bin < 49)
            op[(size_t)c * 49 + bin] = tile[tx][ty + i];
    }
}

extern "C" void kernel_launch(void* const* d_in, const int* in_sizes, int n_in,
                              void* d_out, int out_size)
{
    const float* feat = (const float*)d_in[0];
    const float* rois = (const float*)d_in[1];
    float* out = (float*)d_out;

    dim3 tgrid((HW + 31) / 32, CHANNELS / 32, BATCH);   // 79 x 8 x 4
    dim3 tblk(32, 8);
    transpose_kernel<<<tgrid, tblk>>>(feat);

    int blocks = 128 * 49;   // (roi, bin) = 6272
    roipool_kernel6<<<blocks, 128>>>(rois);

    dim3 ogrid(2, CHANNELS / 32, 128);   // 2 x 8 x 128
    dim3 oblk(32, 8);
    out_transpose_kernel<<<ogrid, oblk>>>(out);
}